// round 1
// baseline (speedup 1.0000x reference)
#include <cuda_runtime.h>

// OTTT step: s, u_new = LIF(sig_tau*u + x@W + b); a_hat_new = sig_tau*a_hat + x
// Inputs (metadata order): W [8192*8192] f32, b [8192], u [8192], a_hat [8192], x [8192]
// Output: flat [s(8192) | u_new(8192) | a_hat_new(8192)] f32

#define IN_DIM  8192
#define OUT_DIM 8192
#define SPLITS  64
#define ROWS_PER_SPLIT (IN_DIM / SPLITS)   // 128
#define TPB     256
#define JPT     4                          // columns per thread (float4)
#define JPB     (TPB * JPT)                // 1024 columns per block
#define JBLOCKS (OUT_DIM / JPB)            // 8

// sigmoid(2.0)
#define SIG_TAU 0.8807970779778823f
#define V_TH    1.0f

// split-K partial sums (2 MB scratch; __device__ global per allocation rules)
__device__ float g_part[(size_t)SPLITS * OUT_DIM];

__global__ void __launch_bounds__(TPB) gemv_partial(
    const float* __restrict__ W, const float* __restrict__ x)
{
    const int jb    = blockIdx.x;           // 0..7
    const int split = blockIdx.y;           // 0..63
    const int j0    = jb * JPB + threadIdx.x * JPT;
    const int i0    = split * ROWS_PER_SPLIT;

    __shared__ float xs[ROWS_PER_SPLIT];
    for (int t = threadIdx.x; t < ROWS_PER_SPLIT; t += TPB)
        xs[t] = x[i0 + t];
    __syncthreads();

    const float4* __restrict__ Wv =
        reinterpret_cast<const float4*>(W + (size_t)i0 * OUT_DIM + j0);
    const size_t row_stride_v4 = OUT_DIM / 4;

    float ax = 0.f, ay = 0.f, az = 0.f, aw = 0.f;

    #pragma unroll 8
    for (int r = 0; r < ROWS_PER_SPLIT; ++r) {
        float4 w = Wv[(size_t)r * row_stride_v4];
        float xv = xs[r];
        ax = fmaf(xv, w.x, ax);
        ay = fmaf(xv, w.y, ay);
        az = fmaf(xv, w.z, az);
        aw = fmaf(xv, w.w, aw);
    }

    float4 acc = make_float4(ax, ay, az, aw);
    *reinterpret_cast<float4*>(g_part + (size_t)split * OUT_DIM + j0) = acc;
}

__global__ void __launch_bounds__(TPB) lif_epilogue(
    const float* __restrict__ b, const float* __restrict__ u,
    const float* __restrict__ a_hat, const float* __restrict__ x,
    float* __restrict__ out)
{
    const int j = blockIdx.x * TPB + threadIdx.x;
    if (j >= OUT_DIM) return;

    float acc = 0.f;
    #pragma unroll
    for (int s = 0; s < SPLITS; ++s)
        acc += g_part[(size_t)s * OUT_DIM + j];

    const float u_pre = fmaf(SIG_TAU, u[j], acc + b[j]);
    const float spike = (u_pre >= V_TH) ? 1.0f : 0.0f;

    out[j]               = spike;                       // s
    out[OUT_DIM + j]     = u_pre - spike * V_TH;        // u_new
    out[2 * OUT_DIM + j] = fmaf(SIG_TAU, a_hat[j], x[j]); // a_hat_new (IN_DIM==OUT_DIM)
}

extern "C" void kernel_launch(void* const* d_in, const int* in_sizes, int n_in,
                              void* d_out, int out_size)
{
    const float* W     = (const float*)d_in[0];
    const float* b     = (const float*)d_in[1];
    const float* u     = (const float*)d_in[2];
    const float* a_hat = (const float*)d_in[3];
    const float* x     = (const float*)d_in[4];
    float* out = (float*)d_out;

    dim3 grid(JBLOCKS, SPLITS);
    gemv_partial<<<grid, TPB>>>(W, x);
    lif_epilogue<<<(OUT_DIM + TPB - 1) / TPB, TPB>>>(b, u, a_hat, x, out);
}

// round 2
// speedup vs baseline: 1.0447x; 1.0447x over previous
#include <cuda_runtime.h>

// OTTT step: s, u_new = LIF(sig_tau*u + x@W + b); a_hat_new = sig_tau*a_hat + x
// Inputs (metadata order): W [8192*8192] f32, b [8192], u [8192], a_hat [8192], x [8192]
// Output: flat [s(8192) | u_new(8192) | a_hat_new(8192)] f32

#define IN_DIM  8192
#define OUT_DIM 8192
#define SPLITS  64
#define ROWS_PER_SPLIT (IN_DIM / SPLITS)   // 128
#define TPB     256
#define JPT     4                          // columns per thread (float4)
#define JPB     (TPB * JPT)                // 1024 columns per block
#define JBLOCKS (OUT_DIM / JPB)            // 8

// sigmoid(2.0)
#define SIG_TAU 0.8807970779778823f
#define V_TH    1.0f

// split-K partial sums (2 MB scratch; __device__ global per allocation rules)
__device__ float g_part[(size_t)SPLITS * OUT_DIM];

__global__ void __launch_bounds__(TPB) gemv_partial(
    const float* __restrict__ W, const float* __restrict__ x)
{
    const int jb    = blockIdx.x;           // 0..7
    const int split = blockIdx.y;           // 0..63
    const int j0    = jb * JPB + threadIdx.x * JPT;
    const int i0    = split * ROWS_PER_SPLIT;

    __shared__ float xs[ROWS_PER_SPLIT];
    for (int t = threadIdx.x; t < ROWS_PER_SPLIT; t += TPB)
        xs[t] = x[i0 + t];
    __syncthreads();

    const float4* __restrict__ Wv =
        reinterpret_cast<const float4*>(W + (size_t)i0 * OUT_DIM + j0);
    const size_t row_stride_v4 = OUT_DIM / 4;

    float ax = 0.f, ay = 0.f, az = 0.f, aw = 0.f;

    #pragma unroll 8
    for (int r = 0; r < ROWS_PER_SPLIT; ++r) {
        // streaming load: W is 268MB, will never be reused — don't thrash L2
        float4 w = __ldcs(Wv + (size_t)r * row_stride_v4);
        float xv = xs[r];
        ax = fmaf(xv, w.x, ax);
        ay = fmaf(xv, w.y, ay);
        az = fmaf(xv, w.z, az);
        aw = fmaf(xv, w.w, aw);
    }

    float4 acc = make_float4(ax, ay, az, aw);
    *reinterpret_cast<float4*>(g_part + (size_t)split * OUT_DIM + j0) = acc;
}

// Epilogue: 64 CTAs x 256 threads. Block covers 128 output columns (32 float4).
// 8 split-groups of 32 lanes each; group g sums splits [g*8, g*8+8).
// Coalesced float4 loads (512B/warp), smem cross-group reduce.
#define EPI_TPB      256
#define EPI_GROUPS   8
#define EPI_SP       (SPLITS / EPI_GROUPS)   // 8
#define EPI_C4       32                       // float4 columns per block
#define EPI_COLS     (EPI_C4 * 4)             // 128
#define EPI_BLOCKS   (OUT_DIM / EPI_COLS)     // 64

__global__ void __launch_bounds__(EPI_TPB) lif_epilogue(
    const float* __restrict__ b, const float* __restrict__ u,
    const float* __restrict__ a_hat, const float* __restrict__ x,
    float* __restrict__ out)
{
    const int g    = threadIdx.x >> 5;        // 0..7 split-group
    const int lane = threadIdx.x & 31;        // 0..31 column (float4)
    const int c4   = blockIdx.x * EPI_C4 + lane;
    const int j0   = c4 * 4;

    const float4* __restrict__ Pv = reinterpret_cast<const float4*>(g_part);
    const size_t row_v4 = OUT_DIM / 4;

    float4 acc = make_float4(0.f, 0.f, 0.f, 0.f);
    #pragma unroll
    for (int s = 0; s < EPI_SP; ++s) {
        float4 p = Pv[(size_t)(g * EPI_SP + s) * row_v4 + c4];
        acc.x += p.x; acc.y += p.y; acc.z += p.z; acc.w += p.w;
    }

    __shared__ float4 red[EPI_GROUPS][EPI_C4];
    red[g][lane] = acc;
    __syncthreads();

    if (g == 0) {
        float4 t = red[0][lane];
        #pragma unroll
        for (int gg = 1; gg < EPI_GROUPS; ++gg) {
            float4 p = red[gg][lane];
            t.x += p.x; t.y += p.y; t.z += p.z; t.w += p.w;
        }
        const float4 bv = reinterpret_cast<const float4*>(b)[c4];
        const float4 uv = reinterpret_cast<const float4*>(u)[c4];

        float4 upre, sv, unew;
        upre.x = fmaf(SIG_TAU, uv.x, t.x + bv.x);
        upre.y = fmaf(SIG_TAU, uv.y, t.y + bv.y);
        upre.z = fmaf(SIG_TAU, uv.z, t.z + bv.z);
        upre.w = fmaf(SIG_TAU, uv.w, t.w + bv.w);
        sv.x = (upre.x >= V_TH) ? 1.0f : 0.0f;
        sv.y = (upre.y >= V_TH) ? 1.0f : 0.0f;
        sv.z = (upre.z >= V_TH) ? 1.0f : 0.0f;
        sv.w = (upre.w >= V_TH) ? 1.0f : 0.0f;
        unew.x = upre.x - sv.x * V_TH;
        unew.y = upre.y - sv.y * V_TH;
        unew.z = upre.z - sv.z * V_TH;
        unew.w = upre.w - sv.w * V_TH;

        reinterpret_cast<float4*>(out)[c4]                 = sv;
        reinterpret_cast<float4*>(out + OUT_DIM)[c4]       = unew;
    } else if (g == 1) {
        // a_hat_new = sig_tau*a_hat + x  (IN_DIM == OUT_DIM, same column range)
        const float4 av = reinterpret_cast<const float4*>(a_hat)[c4];
        const float4 xv = reinterpret_cast<const float4*>(x)[c4];
        float4 an;
        an.x = fmaf(SIG_TAU, av.x, xv.x);
        an.y = fmaf(SIG_TAU, av.y, xv.y);
        an.z = fmaf(SIG_TAU, av.z, xv.z);
        an.w = fmaf(SIG_TAU, av.w, xv.w);
        reinterpret_cast<float4*>(out + 2 * OUT_DIM)[c4] = an;
    }
}

extern "C" void kernel_launch(void* const* d_in, const int* in_sizes, int n_in,
                              void* d_out, int out_size)
{
    const float* W     = (const float*)d_in[0];
    const float* b     = (const float*)d_in[1];
    const float* u     = (const float*)d_in[2];
    const float* a_hat = (const float*)d_in[3];
    const float* x     = (const float*)d_in[4];
    float* out = (float*)d_out;

    dim3 grid(JBLOCKS, SPLITS);
    gemv_partial<<<grid, TPB>>>(W, x);
    lif_epilogue<<<EPI_BLOCKS, EPI_TPB>>>(b, u, a_hat, x, out);
}